// round 8
// baseline (speedup 1.0000x reference)
#include <cuda_runtime.h>

#define B_ 8
#define N_ 8192
#define C_ 6
#define G_ 512
#define K_ 32

#define FPS_CLUSTER 8
#define FPS_THREADS 256
#define FPS_GRID (B_ * FPS_CLUSTER)

// Ascending FMA-chain sum of squares (KNN arithmetic — bitwise-verified).
__device__ __forceinline__ float sq3_fma(float a0, float a1, float a2) {
    float acc = __fmul_rn(a0, a0);
    acc = __fmaf_rn(a1, a1, acc);
    acc = __fmaf_rn(a2, a2, acc);
    return acc;
}

// Blackwell packed fp32x2 (two independent IEEE-rn fp32 ops; bit-identical
// to the verified scalar chain).
#define ADD2(o, a, b) \
    asm("add.rn.f32x2 %0, %1, %2;" : "=l"(o) : "l"(a), "l"(b))
#define MUL2(o, a, b) \
    asm("mul.rn.f32x2 %0, %1, %2;" : "=l"(o) : "l"(a), "l"(b))
#define PACK2(o, lo, hi) \
    asm("mov.b64 %0, {%1, %2};" : "=l"(o) : "f"(lo), "f"(hi))
#define UNPACK2(lo, hi, v) \
    asm("mov.b64 {%0, %1}, %2;" : "=f"(lo), "=f"(hi) : "l"(v))

__device__ __forceinline__ unsigned smem_u32(const void* p) {
    unsigned a;
    asm("{ .reg .u64 t; cvta.to.shared.u64 t, %1; cvt.u32.u64 %0, t; }"
        : "=r"(a) : "l"(p));
    return a;
}
__device__ __forceinline__ unsigned mapa_u32(unsigned a, unsigned rank) {
    unsigned r;
    asm("mapa.shared::cluster.u32 %0, %1, %2;" : "=r"(r) : "r"(a), "r"(rank));
    return r;
}
__device__ __forceinline__ void st_cluster_u64(unsigned a,
                                               unsigned long long v) {
    asm volatile("st.shared::cluster.b64 [%0], %1;" :: "r"(a), "l"(v)
                 : "memory");
}
__device__ __forceinline__ void mbar_init(unsigned a, unsigned cnt) {
    asm volatile("mbarrier.init.shared.b64 [%0], %1;" :: "r"(a), "r"(cnt)
                 : "memory");
}
__device__ __forceinline__ void mbar_arrive_cluster(unsigned a) {
    asm volatile(
        "mbarrier.arrive.release.cluster.shared::cluster.b64 _, [%0];"
        :: "r"(a) : "memory");
}
__device__ __forceinline__ void mbar_wait_cluster(unsigned a, unsigned ph) {
    unsigned done;
    asm volatile(
        "{\n\t.reg .pred p;\n\t"
        "mbarrier.try_wait.parity.acquire.cluster.shared::cta.b64 p, [%1], %2;\n\t"
        "selp.b32 %0, 1, 0, p;\n\t}"
        : "=r"(done) : "r"(a), "r"(ph) : "memory");
    if (!done) {
        asm volatile(
            "{\n\t.reg .pred P1;\n\t"
            "W_%=:\n\t"
            "mbarrier.try_wait.parity.acquire.cluster.shared::cta.b64 P1, [%0], %1, 0x989680;\n\t"
            "@P1 bra.uni D_%=;\n\t"
            "bra.uni W_%=;\n\t"
            "D_%=:\n\t}"
            :: "r"(a), "r"(ph) : "memory");
    }
}
#define CLUSTER_SYNC_() do { \
    asm volatile("barrier.cluster.arrive.aligned;" ::: "memory"); \
    asm volatile("barrier.cluster.wait.aligned;" ::: "memory"); \
} while (0)

// ---------------------------------------------------------------------------
// FPS, cluster-parallel: 8 CTAs per batch (one cluster), 256 threads each,
// 4 points/thread (two f32x2 pairs). Per iteration:
//   compute/min-update (bit-identical chain) -> warp argmax (redux) ->
//   CTA argmax (one __syncthreads) -> all-to-all DSMEM exchange of packed
//   (val, 8191-idx) keys + winner xyz -> every CTA redundantly reduces the
//   8 candidates. Two alternating mbarriers (wait parity (g>>1)&1) give the
//   required distance-2 phase separation; slots double-buffered by g&1.
// ---------------------------------------------------------------------------
__global__ void __launch_bounds__(FPS_THREADS) __cluster_dims__(FPS_CLUSTER, 1, 1)
fps_kernel(const float* __restrict__ pts, float* __restrict__ center_out) {
    const int b    = blockIdx.x >> 3;
    const int rank = blockIdx.x & 7;
    const int tid  = threadIdx.x;
    const int lane = tid & 31;
    const int warp = tid >> 5;

    __shared__ unsigned long long s_slot[2][8][3];  // [par][src][key,xy,z]
    __shared__ unsigned long long s_wkey[8];
    __shared__ unsigned long long s_wxy[8];
    __shared__ unsigned long long s_wz[8];
    __shared__ unsigned long long s_mbar[2];

    const float* base = pts + (size_t)b * N_ * C_;

    // 4 points per thread: p(j) = rank*1024 + tid + j*256, pairs (0,1),(2,3)
    unsigned long long pxv[2], pyv[2], pzv[2];
    unsigned du[4];
#pragma unroll
    for (int j = 0; j < 2; j++) {
        const int p0 = (rank << 10) + tid + ((2 * j) << 8);
        const int p1 = p0 + 256;
        const float2 a01 = *(const float2*)(base + (size_t)p0 * C_);
        const float  a2  = base[(size_t)p0 * C_ + 2];
        const float2 b01 = *(const float2*)(base + (size_t)p1 * C_);
        const float  b2  = base[(size_t)p1 * C_ + 2];
        PACK2(pxv[j], a01.x, b01.x);
        PACK2(pyv[j], a01.y, b01.y);
        PACK2(pzv[j], a2, b2);
        du[2 * j]     = __float_as_uint(1e10f);
        du[2 * j + 1] = __float_as_uint(1e10f);
    }

    const unsigned mb0 = smem_u32(&s_mbar[0]);
    const unsigned mb1 = smem_u32(&s_mbar[1]);
    if (tid == 0) {
        mbar_init(mb0, FPS_CLUSTER);
        mbar_init(mb1, FPS_CLUSTER);
    }
    __syncthreads();
    CLUSTER_SYNC_();  // mbarriers visible cluster-wide before any arrive

    // g = 0 centroid is point 0 of the batch
    float cx = base[0], cy = base[1], cz = base[2];
    if (rank == 0 && tid == 0) {
        float* co = center_out + (size_t)b * G_ * 3;
        co[0] = cx; co[1] = cy; co[2] = cz;
    }

    for (int g = 0; g < G_; g++) {
        unsigned long long ncx, ncy, ncz;
        {
            const float nx = -cx, ny = -cy, nz = -cz;
            PACK2(ncx, nx, nx);
            PACK2(ncy, ny, ny);
            PACK2(ncz, nz, nz);
        }
        unsigned bmax = 0u;
#pragma unroll
        for (int j = 0; j < 2; j++) {
            unsigned long long dx, dy, dz, mx, my, mz, s1, d;
            ADD2(dx, pxv[j], ncx);   // x + (-c) == x - c, bit-exact
            ADD2(dy, pyv[j], ncy);
            ADD2(dz, pzv[j], ncz);
            MUL2(mx, dx, dx);
            MUL2(my, dy, dy);
            MUL2(mz, dz, dz);
            ADD2(s1, mx, my);
            ADD2(d, s1, mz);
            float d0, d1;
            UNPACK2(d0, d1, d);
            du[2 * j]     = umin(du[2 * j],     __float_as_uint(d0));
            du[2 * j + 1] = umin(du[2 * j + 1], __float_as_uint(d1));
            bmax = umax(bmax, umax(du[2 * j], du[2 * j + 1]));
        }
        // first local j attaining bmax (descending keeps smallest index)
        int bi = 0x7fffffff, bj = 0;
#pragma unroll
        for (int j = 3; j >= 0; j--)
            if (du[j] == bmax) { bi = (rank << 10) + tid + (j << 8); bj = j; }

        const unsigned wmax = __reduce_max_sync(0xffffffffu, bmax);
        const int      wmin = __reduce_min_sync(
            0xffffffffu, (bmax == wmax) ? bi : 0x7fffffff);
        if (bmax == wmax && bi == wmin) {
            // winner lane publishes key + its point's xyz
            float lx, hx, ly, hy, lz, hz;
            UNPACK2(lx, hx, pxv[bj >> 1]);
            UNPACK2(ly, hy, pyv[bj >> 1]);
            UNPACK2(lz, hz, pzv[bj >> 1]);
            const float wx = (bj & 1) ? hx : lx;
            const float wy = (bj & 1) ? hy : ly;
            const float wz = (bj & 1) ? hz : lz;
            s_wkey[warp] = ((unsigned long long)wmax << 32) |
                           (unsigned)(8191 - wmin);
            unsigned long long xy, zz;
            PACK2(xy, wx, wy);
            PACK2(zz, wz, wz);
            s_wxy[warp] = xy;
            s_wz[warp]  = zz;
        }
        __syncthreads();

        if (g == G_ - 1) break;
        const int par = g & 1;

        if (warp == 0 && lane < 8) {
            // CTA winner (keys unique -> plain max)
            unsigned long long best = s_wkey[0];
            int w = 0;
#pragma unroll
            for (int t = 1; t < 8; t++)
                if (s_wkey[t] > best) { best = s_wkey[t]; w = t; }
            const unsigned long long kxy = s_wxy[w];
            const unsigned long long kz  = s_wz[w];
            // lane l ships this CTA's candidate to cluster CTA l
            const unsigned dst =
                mapa_u32(smem_u32(&s_slot[par][rank][0]), (unsigned)lane);
            st_cluster_u64(dst,      best);
            st_cluster_u64(dst + 8,  kxy);
            st_cluster_u64(dst + 16, kz);
            mbar_arrive_cluster(
                mapa_u32(par ? mb1 : mb0, (unsigned)lane));
        }

        mbar_wait_cluster(par ? mb1 : mb0, (unsigned)((g >> 1) & 1));

        // all threads redundantly reduce the 8 cluster candidates
        unsigned long long best = s_slot[par][0][0];
        int s = 0;
#pragma unroll
        for (int r = 1; r < 8; r++)
            if (s_slot[par][r][0] > best) { best = s_slot[par][r][0]; s = r; }
        float zlo, zhi;
        UNPACK2(cx, cy, s_slot[par][s][1]);
        UNPACK2(zlo, zhi, s_slot[par][s][2]);
        cz = zlo;

        if (rank == 0 && tid == 0) {
            float* co = center_out + ((size_t)b * G_ + g + 1) * 3;
            co[0] = cx; co[1] = cy; co[2] = cz;
        }
    }
    CLUSTER_SYNC_();
}

// ---------------------------------------------------------------------------
// KNN + gather + center: one CTA per (b, g) center. d2 math bit-identical to
// R4-R7 (rel_err 0.0). Distance phase now loads point PAIRS via 3x LDG.128
// (48 B, aligned). Selection identical to R7.
// ---------------------------------------------------------------------------
__global__ void __launch_bounds__(256) knn_kernel(
    const float* __restrict__ pts, const float* __restrict__ center_in,
    float* __restrict__ nbr_out) {
    __shared__ __align__(16) unsigned s_key[N_];
    __shared__ unsigned s_cmin[64];
    __shared__ int      s_sel[K_];
    __shared__ float    s_ctr[3];

    const int bg   = blockIdx.x;
    const int b    = bg >> 9;  // / G_
    const int tid  = threadIdx.x;
    const int lane = tid & 31;
    const int warp = tid >> 5;

    if (tid < 3) s_ctr[tid] = center_in[(size_t)bg * 3 + tid];
    __syncthreads();
    const float c0 = s_ctr[0], c1 = s_ctr[1], c2 = s_ctr[2];
    const float cc = sq3_fma(c0, c1, c2);

    const float* base = pts + (size_t)b * N_ * C_;
    const float4* b4 = (const float4*)base;
#pragma unroll 4
    for (int q = tid; q < N_ / 2; q += 256) {
        const float4 f0 = b4[3 * q];      // x0 y0 z0 .
        const float4 f1 = b4[3 * q + 1];  // .  .  x1 y1
        const float4 f2 = b4[3 * q + 2];  // z1 .  .  .
        // point 2q
        {
            const float xx = sq3_fma(f0.x, f0.y, f0.z);
            float dot = __fmul_rn(c0, f0.x);
            dot = __fmaf_rn(c1, f0.y, dot);
            dot = __fmaf_rn(c2, f0.z, dot);
            const float d2 =
                __fsub_rn(__fadd_rn(cc, xx), __fmul_rn(2.0f, dot));
            const unsigned bits = __float_as_uint(d2);
            s_key[2 * q] =
                (bits & 0x80000000u) ? ~bits : (bits | 0x80000000u);
        }
        // point 2q+1
        {
            const float xx = sq3_fma(f1.z, f1.w, f2.x);
            float dot = __fmul_rn(c0, f1.z);
            dot = __fmaf_rn(c1, f1.w, dot);
            dot = __fmaf_rn(c2, f2.x, dot);
            const float d2 =
                __fsub_rn(__fadd_rn(cc, xx), __fmul_rn(2.0f, dot));
            const unsigned bits = __float_as_uint(d2);
            s_key[2 * q + 1] =
                (bits & 0x80000000u) ? ~bits : (bits | 0x80000000u);
        }
    }
    __syncthreads();

    // chunk minima: warp w handles chunks [8w, 8w+8); lanes conflict-free
#pragma unroll
    for (int t = 0; t < 8; t++) {
        const int c = (warp << 3) + t;
        const unsigned base_i = (unsigned)(c << 7) + lane;
        const unsigned m =
            umin(umin(s_key[base_i], s_key[base_i + 32]),
                 umin(s_key[base_i + 64], s_key[base_i + 96]));
        const unsigned cm = __reduce_min_sync(0xffffffffu, m);
        if (lane == 0) s_cmin[c] = cm;
    }
    __syncthreads();

    if (warp == 0) {
        for (int k = 0; k < K_; k++) {
            const unsigned a  = s_cmin[lane];
            const unsigned bb = s_cmin[lane + 32];
            const unsigned g  = __reduce_min_sync(0xffffffffu, umin(a, bb));
            const unsigned ba = __ballot_sync(0xffffffffu, a == g);
            const unsigned bB = __ballot_sync(0xffffffffu, bb == g);
            const unsigned c  = ba ? (unsigned)(__ffs(ba) - 1)
                                   : (unsigned)(__ffs(bB) - 1 + 32);

            const unsigned bi = (c << 7) + lane;
            unsigned v0 = s_key[bi];
            unsigned v1 = s_key[bi + 32];
            unsigned v2 = s_key[bi + 64];
            unsigned v3 = s_key[bi + 96];
            const unsigned m0 = __ballot_sync(0xffffffffu, v0 == g);
            const unsigned m1 = __ballot_sync(0xffffffffu, v1 == g);
            const unsigned m2 = __ballot_sync(0xffffffffu, v2 == g);
            const unsigned m3 = __ballot_sync(0xffffffffu, v3 == g);
            unsigned prel;
            if (m0)      prel = (unsigned)(__ffs(m0) - 1);
            else if (m1) prel = (unsigned)(__ffs(m1) - 1 + 32);
            else if (m2) prel = (unsigned)(__ffs(m2) - 1 + 64);
            else         prel = (unsigned)(__ffs(m3) - 1 + 96);
            const unsigned p = (c << 7) + prel;

            if (lane + 0u  == prel) v0 = 0xffffffffu;
            if (lane + 32u == prel) v1 = 0xffffffffu;
            if (lane + 64u == prel) v2 = 0xffffffffu;
            if (lane + 96u == prel) v3 = 0xffffffffu;
            const unsigned nm = __reduce_min_sync(
                0xffffffffu, umin(umin(v0, v1), umin(v2, v3)));
            if (lane == 0) {
                s_sel[k]  = (int)p;
                s_key[p]  = 0xffffffffu;
                s_cmin[c] = nm;
            }
            __syncwarp();
        }
    }
    __syncthreads();

    if (tid < K_ * C_) {
        const int k = tid / C_;
        const int c = tid % C_;
        const int i = s_sel[k];
        float v = base[(size_t)i * C_ + c];
        if (c < 3) v = __fsub_rn(v, s_ctr[c]);
        nbr_out[((size_t)bg * K_ + k) * C_ + c] = v;
    }
}

extern "C" void kernel_launch(void* const* d_in, const int* in_sizes, int n_in,
                              void* d_out, int out_size) {
    const float* pts = (const float*)d_in[0];
    float* out = (float*)d_out;
    float* center_out = out + (size_t)B_ * G_ * K_ * C_;

    fps_kernel<<<FPS_GRID, FPS_THREADS>>>(pts, center_out);
    knn_kernel<<<B_ * G_, 256>>>(pts, center_out, out);
}

// round 9
// speedup vs baseline: 1.5263x; 1.5263x over previous
#include <cuda_runtime.h>

#define B_ 8
#define N_ 8192
#define C_ 6
#define G_ 512
#define K_ 32

// Plain mul/add sum of squares (FPS arithmetic — bitwise-verified).
__device__ __forceinline__ float sq3(float a0, float a1, float a2) {
    return __fadd_rn(__fadd_rn(__fmul_rn(a0, a0), __fmul_rn(a1, a1)),
                     __fmul_rn(a2, a2));
}

// Ascending FMA-chain sum of squares (KNN arithmetic — bitwise-verified).
__device__ __forceinline__ float sq3_fma(float a0, float a1, float a2) {
    float acc = __fmul_rn(a0, a0);
    acc = __fmaf_rn(a1, a1, acc);
    acc = __fmaf_rn(a2, a2, acc);
    return acc;
}

// Blackwell packed fp32x2: two independent IEEE-rn fp32 ops per instruction.
#define ADD2(o, a, b) \
    asm("add.rn.f32x2 %0, %1, %2;" : "=l"(o) : "l"(a), "l"(b))
#define MUL2(o, a, b) \
    asm("mul.rn.f32x2 %0, %1, %2;" : "=l"(o) : "l"(a), "l"(b))
#define PACK2(o, lo, hi) \
    asm("mov.b64 %0, {%1, %2};" : "=l"(o) : "f"(lo), "f"(hi))
#define UNPACK2(lo, hi, v) \
    asm("mov.b64 {%0, %1}, %2;" : "=f"(lo), "=f"(hi) : "l"(v))

// ---------------------------------------------------------------------------
// FPS: R7 version verbatim (320 us, bitwise-verified). Single CTA per batch,
// 1024 threads, 8 points/thread packed two-per-f32x2, one barrier per iter.
// ---------------------------------------------------------------------------
__global__ void __launch_bounds__(1024) fps_kernel(
    const float* __restrict__ pts, float* __restrict__ center_out) {
    const int b    = blockIdx.x;
    const int tid  = threadIdx.x;
    const int lane = tid & 31;
    const int warp = tid >> 5;

    unsigned long long pxv[4], pyv[4], pzv[4];
    unsigned du[8];
    const float* base = pts + (size_t)b * N_ * C_;
#pragma unroll
    for (int j = 0; j < 4; j++) {
        const int p0 = tid + ((2 * j) << 10);
        const int p1 = tid + ((2 * j + 1) << 10);
        const float2 a01 = *(const float2*)(base + (size_t)p0 * C_);
        const float  a2  = base[(size_t)p0 * C_ + 2];
        const float2 b01 = *(const float2*)(base + (size_t)p1 * C_);
        const float  b2  = base[(size_t)p1 * C_ + 2];
        PACK2(pxv[j], a01.x, b01.x);
        PACK2(pyv[j], a01.y, b01.y);
        PACK2(pzv[j], a2, b2);
        du[2 * j]     = __float_as_uint(1e10f);
        du[2 * j + 1] = __float_as_uint(1e10f);
    }

    __shared__ unsigned s_wv[2][32];
    __shared__ int      s_wi[2][32];

    int far = 0;
    for (int g = 0; g < G_; g++) {
        const int par = g & 1;
        const float* cq = base + (size_t)far * C_;
        const float2 cxy = *(const float2*)cq;
        const float cx = cxy.x, cy = cxy.y, cz = cq[2];
        if (tid == 0) {
            float* co = center_out + ((size_t)b * G_ + g) * 3;
            co[0] = cx; co[1] = cy; co[2] = cz;
        }
        unsigned long long ncx, ncy, ncz;
        {
            const float nx = -cx, ny = -cy, nz = -cz;
            PACK2(ncx, nx, nx);
            PACK2(ncy, ny, ny);
            PACK2(ncz, nz, nz);
        }

        unsigned bmax = 0u;
#pragma unroll
        for (int j = 0; j < 4; j++) {
            unsigned long long dx, dy, dz, mx, my, mz, s1, d;
            ADD2(dx, pxv[j], ncx);          // x + (-c) == x - c, bit-exact
            ADD2(dy, pyv[j], ncy);
            ADD2(dz, pzv[j], ncz);
            MUL2(mx, dx, dx);
            MUL2(my, dy, dy);
            MUL2(mz, dz, dz);
            ADD2(s1, mx, my);
            ADD2(d, s1, mz);
            float d0, d1;
            UNPACK2(d0, d1, d);
            du[2 * j]     = umin(du[2 * j],     __float_as_uint(d0));
            du[2 * j + 1] = umin(du[2 * j + 1], __float_as_uint(d1));
            bmax = umax(bmax, umax(du[2 * j], du[2 * j + 1]));
        }
        int bi = 0x7fffffff;
#pragma unroll
        for (int j = 7; j >= 0; j--)
            if (du[j] == bmax) bi = tid + (j << 10);

        const unsigned wmax = __reduce_max_sync(0xffffffffu, bmax);
        const int      wmin = __reduce_min_sync(
            0xffffffffu, (bmax == wmax) ? bi : 0x7fffffff);
        if (lane == 0) { s_wv[par][warp] = wmax; s_wi[par][warp] = wmin; }
        __syncthreads();  // the only barrier per iteration

        const unsigned v = s_wv[par][lane];
        const int      i = s_wi[par][lane];
        const unsigned gm = __reduce_max_sync(0xffffffffu, v);
        far = __reduce_min_sync(0xffffffffu, (v == gm) ? i : 0x7fffffff);
    }
}

// ---------------------------------------------------------------------------
// KNN + gather + center: one CTA per (b, g) center. d2 math bit-identical to
// R4-R7. Warp-per-chunk distance phase: warp w computes chunks [8w, 8w+8),
// lane l handles points c*128 + l + {0,32,64,96}; chunk minima reduced from
// registers (no second smem pass). Selection in warp 0 with REGISTER-resident
// chunk minima; ballot+ffs index finding (exact top_k tie order).
// ---------------------------------------------------------------------------
__global__ void __launch_bounds__(256) knn_kernel(
    const float* __restrict__ pts, const float* __restrict__ center_in,
    float* __restrict__ nbr_out) {
    __shared__ __align__(16) unsigned s_key[N_];
    __shared__ unsigned s_cmin[64];
    __shared__ int      s_sel[K_];
    __shared__ float    s_ctr[3];

    const int bg   = blockIdx.x;
    const int b    = bg >> 9;  // / G_
    const int tid  = threadIdx.x;
    const int lane = tid & 31;
    const int warp = tid >> 5;

    if (tid < 3) s_ctr[tid] = center_in[(size_t)bg * 3 + tid];
    __syncthreads();
    const float c0 = s_ctr[0], c1 = s_ctr[1], c2 = s_ctr[2];
    const float cc = sq3_fma(c0, c1, c2);

    const float* base = pts + (size_t)b * N_ * C_;

    // distance + chunk-min fused: warp w owns chunks [8w, 8w+8)
#pragma unroll
    for (int t = 0; t < 8; t++) {
        const int c = (warp << 3) + t;
        unsigned mloc = 0xffffffffu;
#pragma unroll
        for (int s = 0; s < 4; s++) {
            const int n = (c << 7) + lane + (s << 5);
            const float2 xy = *(const float2*)(base + (size_t)n * C_);
            const float x0 = xy.x, x1 = xy.y;
            const float x2 = base[(size_t)n * C_ + 2];
            const float xx = sq3_fma(x0, x1, x2);
            float dot = __fmul_rn(c0, x0);
            dot = __fmaf_rn(c1, x1, dot);
            dot = __fmaf_rn(c2, x2, dot);
            const float d2 =
                __fsub_rn(__fadd_rn(cc, xx), __fmul_rn(2.0f, dot));
            const unsigned bits = __float_as_uint(d2);
            const unsigned key =
                (bits & 0x80000000u) ? ~bits : (bits | 0x80000000u);
            s_key[n] = key;
            mloc = umin(mloc, key);
        }
        const unsigned cm = __reduce_min_sync(0xffffffffu, mloc);
        if (lane == 0) s_cmin[c] = cm;
    }
    __syncthreads();

    if (warp == 0) {
        // chunk minima live in registers across the whole selection loop
        unsigned a  = s_cmin[lane];
        unsigned bb = s_cmin[lane + 32];
        for (int k = 0; k < K_; k++) {
            const unsigned g  = __reduce_min_sync(0xffffffffu, umin(a, bb));
            const unsigned ba = __ballot_sync(0xffffffffu, a == g);
            const unsigned bB = __ballot_sync(0xffffffffu, bb == g);
            const unsigned c  = ba ? (unsigned)(__ffs(ba) - 1)
                                   : (unsigned)(__ffs(bB) - 1 + 32);

            const unsigned bi = (c << 7) + lane;
            unsigned v0 = s_key[bi];
            unsigned v1 = s_key[bi + 32];
            unsigned v2 = s_key[bi + 64];
            unsigned v3 = s_key[bi + 96];
            const unsigned m0 = __ballot_sync(0xffffffffu, v0 == g);
            const unsigned m1 = __ballot_sync(0xffffffffu, v1 == g);
            const unsigned m2 = __ballot_sync(0xffffffffu, v2 == g);
            const unsigned m3 = __ballot_sync(0xffffffffu, v3 == g);
            unsigned prel;
            if (m0)      prel = (unsigned)(__ffs(m0) - 1);
            else if (m1) prel = (unsigned)(__ffs(m1) - 1 + 32);
            else if (m2) prel = (unsigned)(__ffs(m2) - 1 + 64);
            else         prel = (unsigned)(__ffs(m3) - 1 + 96);
            const unsigned p = (c << 7) + prel;

            // poison winner in registers, recompute this chunk's min
            if (lane + 0u  == prel) v0 = 0xffffffffu;
            if (lane + 32u == prel) v1 = 0xffffffffu;
            if (lane + 64u == prel) v2 = 0xffffffffu;
            if (lane + 96u == prel) v3 = 0xffffffffu;
            const unsigned nm = __reduce_min_sync(
                0xffffffffu, umin(umin(v0, v1), umin(v2, v3)));

            if (lane == 0) {
                s_sel[k] = (int)p;
                s_key[p] = 0xffffffffu;  // for future rescans of this chunk
            }
            // register update of the winning chunk's min
            if (c == (unsigned)lane)        a  = nm;
            else if (c == (unsigned)lane + 32u) bb = nm;
            __syncwarp();  // make lane0's s_key poison visible warp-wide
        }
    }
    __syncthreads();

    // Gather neighborhoods and center the xyz channels.
    if (tid < K_ * C_) {
        const int k = tid / C_;
        const int c = tid % C_;
        const int i = s_sel[k];
        float v = base[(size_t)i * C_ + c];
        if (c < 3) v = __fsub_rn(v, s_ctr[c]);
        nbr_out[((size_t)bg * K_ + k) * C_ + c] = v;
    }
}

extern "C" void kernel_launch(void* const* d_in, const int* in_sizes, int n_in,
                              void* d_out, int out_size) {
    const float* pts = (const float*)d_in[0];
    float* out = (float*)d_out;
    float* center_out = out + (size_t)B_ * G_ * K_ * C_;

    fps_kernel<<<B_, 1024>>>(pts, center_out);
    knn_kernel<<<B_ * G_, 256>>>(pts, center_out, out);
}